// round 2
// baseline (speedup 1.0000x reference)
#include <cuda_runtime.h>

#define NN 1024
#define BB 128

// Scratch (static device globals; no allocation)
__device__ float g_EWt[NN * NN];      // EWt[k][i] = exp(W[i][k])
__device__ float g_part[32 * NN];     // per-i-tile column partial sums
__device__ float g_c[NN];             // c[k] = log sum_i exp(W[i][k])
__device__ float g_At[NN * BB];       // At[k][b] = exp(la[b][k] - c[k] - m[b])
__device__ float g_m[BB];             // m[b]

// ---------------------------------------------------------------------------
// k1: tiled transpose + exp + column partial sums
// grid (32 k-tiles, 32 i-tiles), block (32, 8)
// ---------------------------------------------------------------------------
__global__ void k1_exp_transpose(const float* __restrict__ W) {
    __shared__ float sm[32][33];
    const int k0 = blockIdx.x * 32, i0 = blockIdx.y * 32;
    const int tx = threadIdx.x, ty = threadIdx.y;

#pragma unroll
    for (int j = 0; j < 4; j++) {
        int il = ty + 8 * j;
        sm[il][tx] = __expf(W[(size_t)(i0 + il) * NN + (k0 + tx)]);
    }
    __syncthreads();

    // transposed, coalesced write: EWt[k][i]
#pragma unroll
    for (int j = 0; j < 4; j++) {
        int kl = ty + 8 * j;
        g_EWt[(size_t)(k0 + kl) * NN + (i0 + tx)] = sm[tx][kl];
    }

    // column sums over i for column k0+tx
    float s = 0.f;
#pragma unroll
    for (int j = 0; j < 4; j++) s += sm[ty + 8 * j][tx];

    __shared__ float red[8][32];
    red[ty][tx] = s;
    __syncthreads();
    if (ty == 0) {
        float t = 0.f;
#pragma unroll
        for (int y = 0; y < 8; y++) t += red[y][tx];
        g_part[blockIdx.y * NN + (k0 + tx)] = t;
    }
}

// ---------------------------------------------------------------------------
// k2: c[k] = log(sum of 32 partials)
// grid 4, block 256
// ---------------------------------------------------------------------------
__global__ void k2_colnorm() {
    int k = blockIdx.x * 256 + threadIdx.x;
    float s = 0.f;
#pragma unroll
    for (int t = 0; t < 32; t++) s += g_part[t * NN + k];
    g_c[k] = logf(s);
}

// ---------------------------------------------------------------------------
// k3: per-batch m[b] + At[k][b] = exp(la - c - m)
// grid BB, block 256 (4 k per thread)
// ---------------------------------------------------------------------------
__global__ void k3_alpha(const float* __restrict__ la) {
    const int b = blockIdx.x, t = threadIdx.x;
    float4 lv = reinterpret_cast<const float4*>(la + (size_t)b * NN)[t];
    float4 cv = reinterpret_cast<const float4*>(g_c)[t];
    float v0 = lv.x - cv.x, v1 = lv.y - cv.y, v2 = lv.z - cv.z, v3 = lv.w - cv.w;
    float mx = fmaxf(fmaxf(v0, v1), fmaxf(v2, v3));
#pragma unroll
    for (int o = 16; o > 0; o >>= 1) mx = fmaxf(mx, __shfl_xor_sync(0xffffffffu, mx, o));
    __shared__ float wred[8];
    if ((t & 31) == 0) wred[t >> 5] = mx;
    __syncthreads();
    float m2 = wred[0];
#pragma unroll
    for (int w = 1; w < 8; w++) m2 = fmaxf(m2, wred[w]);

    const int k = 4 * t;
    g_At[(size_t)(k + 0) * BB + b] = __expf(v0 - m2);
    g_At[(size_t)(k + 1) * BB + b] = __expf(v1 - m2);
    g_At[(size_t)(k + 2) * BB + b] = __expf(v2 - m2);
    g_At[(size_t)(k + 3) * BB + b] = __expf(v3 - m2);
    if (t == 0) g_m[b] = m2;
}

// ---------------------------------------------------------------------------
// k4: GEMM  acc[b][i] = sum_k At[k][b] * EWt[k][i],  out = log(acc) + m[b]
// BM=32 (b), BN=32 (i), BK=32, 64 threads, 4x4 register tile, double-buffered
// grid (32 i-tiles, 4 b-tiles)
// ---------------------------------------------------------------------------
__global__ void __launch_bounds__(64) k4_gemm(float* __restrict__ out) {
    __shared__ float As[2][32][36];  // [k][m], 144B rows (16B aligned)
    __shared__ float Es[2][32][36];  // [k][n]
    const int i0 = blockIdx.x * 32, b0 = blockIdx.y * 32;
    const int tid = threadIdx.x;
    const int tm = tid & 7, tn = tid >> 3;   // thread tile coords (8 x 8)
    const int lr = tid >> 3, lf = tid & 7;   // load coords: row-in-chunk, float4 idx

    float4 ra[4], re[4];
#pragma unroll
    for (int q = 0; q < 4; q++) {
        int kk = lr + 8 * q;
        ra[q] = *reinterpret_cast<const float4*>(&g_At[(size_t)kk * BB + b0 + lf * 4]);
        re[q] = *reinterpret_cast<const float4*>(&g_EWt[(size_t)kk * NN + i0 + lf * 4]);
    }
    int buf = 0;
#pragma unroll
    for (int q = 0; q < 4; q++) {
        int kk = lr + 8 * q;
        *reinterpret_cast<float4*>(&As[buf][kk][lf * 4]) = ra[q];
        *reinterpret_cast<float4*>(&Es[buf][kk][lf * 4]) = re[q];
    }
    __syncthreads();

    float acc[4][4];
#pragma unroll
    for (int r = 0; r < 4; r++)
#pragma unroll
        for (int s = 0; s < 4; s++) acc[r][s] = 0.f;

    const int NC = NN / 32;
    for (int c = 0; c < NC; c++) {
        if (c + 1 < NC) {
            const int k0n = (c + 1) * 32;
#pragma unroll
            for (int q = 0; q < 4; q++) {
                int kk = k0n + lr + 8 * q;
                ra[q] = *reinterpret_cast<const float4*>(&g_At[(size_t)kk * BB + b0 + lf * 4]);
                re[q] = *reinterpret_cast<const float4*>(&g_EWt[(size_t)kk * NN + i0 + lf * 4]);
            }
        }
#pragma unroll
        for (int kk = 0; kk < 32; kk++) {
            float4 a = *reinterpret_cast<const float4*>(&As[buf][kk][tm * 4]);
            float4 e = *reinterpret_cast<const float4*>(&Es[buf][kk][tn * 4]);
            float av[4] = {a.x, a.y, a.z, a.w};
            float ev[4] = {e.x, e.y, e.z, e.w};
#pragma unroll
            for (int r = 0; r < 4; r++)
#pragma unroll
                for (int s = 0; s < 4; s++) acc[r][s] = fmaf(av[r], ev[s], acc[r][s]);
        }
        if (c + 1 < NC) {
            __syncthreads();
#pragma unroll
            for (int q = 0; q < 4; q++) {
                int kk = lr + 8 * q;
                *reinterpret_cast<float4*>(&As[buf ^ 1][kk][lf * 4]) = ra[q];
                *reinterpret_cast<float4*>(&Es[buf ^ 1][kk][lf * 4]) = re[q];
            }
            __syncthreads();
            buf ^= 1;
        }
    }

    // epilogue: out[b][i] = log(acc) + m[b]
#pragma unroll
    for (int r = 0; r < 4; r++) {
        const int b = b0 + tm * 4 + r;
        const float mb = g_m[b];
        float4 o;
        o.x = logf(acc[r][0]) + mb;
        o.y = logf(acc[r][1]) + mb;
        o.z = logf(acc[r][2]) + mb;
        o.w = logf(acc[r][3]) + mb;
        *reinterpret_cast<float4*>(&out[(size_t)b * NN + i0 + tn * 4]) = o;
    }
}

// ---------------------------------------------------------------------------
extern "C" void kernel_launch(void* const* d_in, const int* in_sizes, int n_in,
                              void* d_out, int out_size) {
    const float* la;
    const float* W;
    if (in_sizes[0] == BB * NN) {
        la = (const float*)d_in[0];
        W  = (const float*)d_in[1];
    } else {
        W  = (const float*)d_in[0];
        la = (const float*)d_in[1];
    }
    float* out = (float*)d_out;

    k1_exp_transpose<<<dim3(32, 32), dim3(32, 8)>>>(W);
    k2_colnorm<<<4, 256>>>();
    k3_alpha<<<BB, 256>>>(la);
    k4_gemm<<<dim3(32, 4), 64>>>(out);
}

// round 5
// speedup vs baseline: 1.3282x; 1.3282x over previous
#include <cuda_runtime.h>

#define NN 1024
#define BB 128
#define KS 8            // split-K factor
#define KCHUNK (NN / KS)  // 128

// Scratch (static device globals; no allocation)
__device__ float g_EWt[NN * NN];        // EWt[k][i] = exp(W[i][k])
__device__ float g_part[32 * NN];       // per-i-tile column partial sums
__device__ float g_c[NN];               // c[k] = log sum_i exp(W[i][k])
__device__ float g_At[NN * BB];         // At[k][b] = exp(la[b][k] - c[k] - m[b])
__device__ float g_m[BB];               // m[b]
__device__ float g_ps[KS * BB * NN];    // split-K partial sums

// ---------------------------------------------------------------------------
// k1: tiled transpose + exp + column partial sums
// grid (32 k-tiles, 32 i-tiles), block (32, 8)
// ---------------------------------------------------------------------------
__global__ void k1_exp_transpose(const float* __restrict__ W) {
    __shared__ float sm[32][33];
    const int k0 = blockIdx.x * 32, i0 = blockIdx.y * 32;
    const int tx = threadIdx.x, ty = threadIdx.y;

#pragma unroll
    for (int j = 0; j < 4; j++) {
        int il = ty + 8 * j;
        sm[il][tx] = __expf(W[(size_t)(i0 + il) * NN + (k0 + tx)]);
    }
    __syncthreads();

#pragma unroll
    for (int j = 0; j < 4; j++) {
        int kl = ty + 8 * j;
        g_EWt[(size_t)(k0 + kl) * NN + (i0 + tx)] = sm[tx][kl];
    }

    float s = 0.f;
#pragma unroll
    for (int j = 0; j < 4; j++) s += sm[ty + 8 * j][tx];

    __shared__ float red[8][32];
    red[ty][tx] = s;
    __syncthreads();
    if (ty == 0) {
        float t = 0.f;
#pragma unroll
        for (int y = 0; y < 8; y++) t += red[y][tx];
        g_part[blockIdx.y * NN + (k0 + tx)] = t;
    }
}

// ---------------------------------------------------------------------------
// k2: c[k] = log(sum of 32 partials)
// ---------------------------------------------------------------------------
__global__ void k2_colnorm() {
    int k = blockIdx.x * 256 + threadIdx.x;
    float s = 0.f;
#pragma unroll
    for (int t = 0; t < 32; t++) s += g_part[t * NN + k];
    g_c[k] = logf(s);
}

// ---------------------------------------------------------------------------
// k3: per-batch m[b] + At[k][b] = exp(la - c - m)
// ---------------------------------------------------------------------------
__global__ void k3_alpha(const float* __restrict__ la) {
    const int b = blockIdx.x, t = threadIdx.x;
    float4 lv = reinterpret_cast<const float4*>(la + (size_t)b * NN)[t];
    float4 cv = reinterpret_cast<const float4*>(g_c)[t];
    float v0 = lv.x - cv.x, v1 = lv.y - cv.y, v2 = lv.z - cv.z, v3 = lv.w - cv.w;
    float mx = fmaxf(fmaxf(v0, v1), fmaxf(v2, v3));
#pragma unroll
    for (int o = 16; o > 0; o >>= 1) mx = fmaxf(mx, __shfl_xor_sync(0xffffffffu, mx, o));
    __shared__ float wred[8];
    if ((t & 31) == 0) wred[t >> 5] = mx;
    __syncthreads();
    float m2 = wred[0];
#pragma unroll
    for (int w = 1; w < 8; w++) m2 = fmaxf(m2, wred[w]);

    const int k = 4 * t;
    g_At[(size_t)(k + 0) * BB + b] = __expf(v0 - m2);
    g_At[(size_t)(k + 1) * BB + b] = __expf(v1 - m2);
    g_At[(size_t)(k + 2) * BB + b] = __expf(v2 - m2);
    g_At[(size_t)(k + 3) * BB + b] = __expf(v3 - m2);
    if (t == 0) g_m[b] = m2;
}

// ---------------------------------------------------------------------------
// k4: split-K GEMM partial:  ps[z][b][i] += sum_{k in chunk z} At[k][b]*EWt[k][i]
// BM=32 (b), BN=128 (i), BK=32, 128 threads, 8x4 register tile, double-buffered
// grid (8 i-tiles, 4 b-tiles, KS k-chunks)
// ---------------------------------------------------------------------------
__global__ void __launch_bounds__(128) k4_gemm() {
    __shared__ float As[2][32][36];    // [k][b]  (32 + 4 pad)
    __shared__ float Es[2][32][132];   // [k][i]  (128 + 4 pad)
    const int i0 = blockIdx.x * 128, b0 = blockIdx.y * 32;
    const int kbase = blockIdx.z * KCHUNK;
    const int tid = threadIdx.x;
    const int tm = tid & 3;            // 4 groups of 8 b-rows
    const int tn = tid >> 2;           // 32 groups of 4 i-cols

    float4 ra[2], re[8];

    // global prefetch of one BK=32 sub-chunk starting at k0
#define LOADG(k0)                                                                 \
    {                                                                             \
        _Pragma("unroll") for (int q = 0; q < 2; q++) {                           \
            int idx = tid + q * 128, r = idx >> 3, f = idx & 7;                   \
            ra[q] = *reinterpret_cast<const float4*>(                             \
                &g_At[(size_t)((k0) + r) * BB + b0 + f * 4]);                     \
        }                                                                         \
        _Pragma("unroll") for (int p = 0; p < 8; p++) {                           \
            int idx = tid + p * 128, r = idx >> 5, f = idx & 31;                  \
            re[p] = *reinterpret_cast<const float4*>(                             \
                &g_EWt[(size_t)((k0) + r) * NN + i0 + f * 4]);                    \
        }                                                                         \
    }

#define STORES(bf)                                                                \
    {                                                                             \
        _Pragma("unroll") for (int q = 0; q < 2; q++) {                           \
            int idx = tid + q * 128, r = idx >> 3, f = idx & 7;                   \
            *reinterpret_cast<float4*>(&As[bf][r][f * 4]) = ra[q];                \
        }                                                                         \
        _Pragma("unroll") for (int p = 0; p < 8; p++) {                           \
            int idx = tid + p * 128, r = idx >> 5, f = idx & 31;                  \
            *reinterpret_cast<float4*>(&Es[bf][r][f * 4]) = re[p];                \
        }                                                                         \
    }

    LOADG(kbase);
    STORES(0);
    __syncthreads();

    float acc[8][4];
#pragma unroll
    for (int r = 0; r < 8; r++)
#pragma unroll
        for (int s = 0; s < 4; s++) acc[r][s] = 0.f;

    const int NSUB = KCHUNK / 32;  // 4
    int buf = 0;
    for (int c = 0; c < NSUB; c++) {
        if (c + 1 < NSUB) LOADG(kbase + (c + 1) * 32);
#pragma unroll
        for (int kk = 0; kk < 32; kk++) {
            float4 a0 = *reinterpret_cast<const float4*>(&As[buf][kk][tm * 8]);
            float4 a1 = *reinterpret_cast<const float4*>(&As[buf][kk][tm * 8 + 4]);
            float4 e  = *reinterpret_cast<const float4*>(&Es[buf][kk][tn * 4]);
            float av[8] = {a0.x, a0.y, a0.z, a0.w, a1.x, a1.y, a1.z, a1.w};
            float ev[4] = {e.x, e.y, e.z, e.w};
#pragma unroll
            for (int r = 0; r < 8; r++)
#pragma unroll
                for (int s = 0; s < 4; s++) acc[r][s] = fmaf(av[r], ev[s], acc[r][s]);
        }
        if (c + 1 < NSUB) {
            __syncthreads();
            STORES(buf ^ 1);
            __syncthreads();
            buf ^= 1;
        }
    }

    // write fp32 partials (no log here)
    float* ps = g_ps + (size_t)blockIdx.z * BB * NN;
#pragma unroll
    for (int r = 0; r < 8; r++) {
        const int b = b0 + tm * 8 + r;
        float4 o = make_float4(acc[r][0], acc[r][1], acc[r][2], acc[r][3]);
        *reinterpret_cast<float4*>(&ps[(size_t)b * NN + i0 + tn * 4]) = o;
    }
#undef LOADG
#undef STORES
}

// ---------------------------------------------------------------------------
// k5: reduce KS partials, out = log(sum) + m[b]
// grid 128, block 256; one float4 per thread
// ---------------------------------------------------------------------------
__global__ void k5_reduce(float* __restrict__ out) {
    const int idx = blockIdx.x * 256 + threadIdx.x;  // float4 index, 32768 total
    const int b = idx >> 8;                          // 256 float4 per b-row
    const float4* p = reinterpret_cast<const float4*>(g_ps);
    float4 s = p[idx];
#pragma unroll
    for (int z = 1; z < KS; z++) {
        float4 v = p[(size_t)z * (BB * NN / 4) + idx];
        s.x += v.x; s.y += v.y; s.z += v.z; s.w += v.w;
    }
    const float mb = g_m[b];
    float4 o;
    o.x = logf(s.x) + mb;
    o.y = logf(s.y) + mb;
    o.z = logf(s.z) + mb;
    o.w = logf(s.w) + mb;
    reinterpret_cast<float4*>(out)[idx] = o;
}

// ---------------------------------------------------------------------------
extern "C" void kernel_launch(void* const* d_in, const int* in_sizes, int n_in,
                              void* d_out, int out_size) {
    const float* la;
    const float* W;
    if (in_sizes[0] == BB * NN) {
        la = (const float*)d_in[0];
        W  = (const float*)d_in[1];
    } else {
        W  = (const float*)d_in[0];
        la = (const float*)d_in[1];
    }
    float* out = (float*)d_out;

    k1_exp_transpose<<<dim3(32, 32), dim3(32, 8)>>>(W);
    k2_colnorm<<<4, 256>>>();
    k3_alpha<<<BB, 256>>>(la);
    k4_gemm<<<dim3(8, 4, KS), 128>>>();
    k5_reduce<<<128, 256>>>(out);
}